// round 15
// baseline (speedup 1.0000x reference)
#include <cuda_runtime.h>
#include <cuda_fp16.h>
#include <cstdint>

#define Bz 2
#define Tt 2048
#define Dd 2048
#define Hh 16
#define HD 128
#define Mrows (Bz*Tt)
#define QKVS (Bz*Hh*Tt*HD)

// Scratch (static device globals: allocation-free, graph-capture safe)
__device__ __half g_qkvh[3*QKVS];       // Q|K|V [sel][B,H,T,HD] fp16
__device__ __half g_xh[Mrows*Dd];       // x in fp16
__device__ __half g_wh[4*Dd*Dd];        // Wq|Wk|Wv|Wo in fp16
__device__ __half g_ah[Mrows*Dd];       // attention output [B,T,D] fp16

__device__ __forceinline__ void mma16816h(float* d, const uint32_t* a,
                                          const uint32_t* b, const float* c) {
    asm volatile(
        "mma.sync.aligned.m16n8k16.row.col.f32.f16.f16.f32 "
        "{%0,%1,%2,%3}, {%4,%5,%6,%7}, {%8,%9}, {%10,%11,%12,%13};"
        : "=f"(d[0]), "=f"(d[1]), "=f"(d[2]), "=f"(d[3])
        : "r"(a[0]), "r"(a[1]), "r"(a[2]), "r"(a[3]),
          "r"(b[0]), "r"(b[1]),
          "f"(c[0]), "f"(c[1]), "f"(c[2]), "f"(c[3]));
}
__device__ __forceinline__ void ldsm4(uint32_t* r, uint32_t addr) {
    asm volatile("ldmatrix.sync.aligned.m8n8.x4.shared.b16 {%0,%1,%2,%3}, [%4];"
        : "=r"(r[0]), "=r"(r[1]), "=r"(r[2]), "=r"(r[3]) : "r"(addr));
}
__device__ __forceinline__ void ldsm4t(uint32_t* r, uint32_t addr) {
    asm volatile("ldmatrix.sync.aligned.m8n8.x4.trans.shared.b16 {%0,%1,%2,%3}, [%4];"
        : "=r"(r[0]), "=r"(r[1]), "=r"(r[2]), "=r"(r[3]) : "r"(addr));
}
__device__ __forceinline__ uint32_t smem_u32(const void* p) {
    uint32_t a;
    asm("{ .reg .u64 t; cvta.to.shared.u64 t, %1; cvt.u32.u64 %0, t; }" : "=r"(a) : "l"(p));
    return a;
}
__device__ __forceinline__ void cp16(uint32_t dst, const void* src) {
    asm volatile("cp.async.cg.shared.global [%0], [%1], 16;" :: "r"(dst), "l"(src));
}

// ===========================================================================
// fp32 -> fp16 conversion pre-pass (x + 4 weights)
// ===========================================================================
__global__ __launch_bounds__(256) void cvt_fp16(
    const float* __restrict__ x,
    const float* __restrict__ wq, const float* __restrict__ wk,
    const float* __restrict__ wv, const float* __restrict__ wo)
{
    const int sel = blockIdx.y;
    const float* src = (sel == 0) ? x : (sel == 1) ? wq : (sel == 2) ? wk
                       : (sel == 3) ? wv : wo;
    __half* dst = (sel == 0) ? g_xh : g_wh + (size_t)(sel - 1) * Dd * Dd;
    const int n = (sel == 0) ? Mrows * Dd : Dd * Dd;
    const int stride = gridDim.x * blockDim.x * 4;
    for (int i = (blockIdx.x * blockDim.x + threadIdx.x) * 4; i < n; i += stride) {
        float4 v = *(const float4*)(src + i);
        *(__half2*)(dst + i) = __floats2half2_rn(v.x, v.y);
        *(__half2*)(dst + i + 2) = __floats2half2_rn(v.z, v.w);
    }
}

// ===========================================================================
// mma.sync fp16 GEMM v5 (NT): C = A B^T (+bias), fp32 accum.
// 128 threads, 4 warps, warp tile 64x64. CTA 128x128, BK=64 (half the
// barriers of v4), 2-stage cp.async, register-double-buffered LDSM fragments.
// ===========================================================================
#define TBM 128
#define TBN 128
#define GBK 64
#define GNKT (Dd / GBK)           // 32
#define GSTR 36                   // words per row: 32 data + 4 pad
#define GTILE_W (128 * GSTR)      // 4608 words per operand tile
#define TCH_SMEM (2 * 2 * GTILE_W * 4)  // 73728 B -> 2 CTAs/SM

__global__ __launch_bounds__(128, 2) void tc_gemm_h(
    const __half* __restrict__ A, const __half* __restrict__ B,
    const float* __restrict__ bias, float* __restrict__ Cf,
    __half* __restrict__ Ch, int qkv_mode)
{
    extern __shared__ uint32_t smw[];
    const uint32_t sbase = smem_u32(smw);

    const int tid = threadIdx.x;
    const int wid = tid >> 5;
    const int lane = tid & 31;
    const int grp = lane >> 2;
    const int tig = lane & 3;
    const int wm = (wid >> 1) * 64;
    const int wn = (wid & 1) * 64;
    const int row0 = blockIdx.y * TBM;
    const int col0 = blockIdx.x * TBN;

    const int rowA = wm + (lane & 15);
    const int colA = ((lane >> 4) << 2);
    const int rowB = wn + ((lane >> 4) << 3) + (lane & 7);
    const int colB = (((lane >> 3) & 1) << 2);

    // copy coords: 1024 x 16B chunks per operand tile, 128 threads -> 8 each
    int lr[8], lwc[8], lhc[8];
    #pragma unroll
    for (int i = 0; i < 8; i++) {
        int c = tid + i * 128;       // 0..1023
        lr[i] = c >> 3;              // row 0..127
        lwc[i] = (c & 7) * 4;        // word col
        lhc[i] = (c & 7) * 8;        // half col
    }

    float acc[4][8][4];
    #pragma unroll
    for (int mt = 0; mt < 4; mt++)
        #pragma unroll
        for (int nt = 0; nt < 8; nt++)
            #pragma unroll
            for (int e = 0; e < 4; e++) acc[mt][nt][e] = 0.f;

    // ---- prologue: stage 0
    #pragma unroll
    for (int i = 0; i < 8; i++) {
        uint32_t so = (uint32_t)((lr[i] * GSTR + lwc[i]) * 4);
        cp16(sbase + so, A + (size_t)(row0 + lr[i]) * Dd + lhc[i]);
        cp16(sbase + GTILE_W * 4 + so, B + (size_t)(col0 + lr[i]) * Dd + lhc[i]);
    }
    asm volatile("cp.async.commit_group;");

    for (int kt = 0; kt < GNKT; kt++) {
        asm volatile("cp.async.wait_group 0;");
        __syncthreads();   // tile kt visible; buffer kt+1 free (compute kt-1 done)

        if (kt + 1 < GNKT) {
            const uint32_t buf = sbase + (uint32_t)((kt + 1) & 1) * 2u * GTILE_W * 4u;
            const int k0 = (kt + 1) * GBK;
            #pragma unroll
            for (int i = 0; i < 8; i++) {
                uint32_t so = (uint32_t)((lr[i] * GSTR + lwc[i]) * 4);
                cp16(buf + so, A + (size_t)(row0 + lr[i]) * Dd + k0 + lhc[i]);
                cp16(buf + GTILE_W * 4 + so, B + (size_t)(col0 + lr[i]) * Dd + k0 + lhc[i]);
            }
            asm volatile("cp.async.commit_group;");
        }

        const uint32_t bufA = sbase + (uint32_t)(kt & 1) * 2u * GTILE_W * 4u;
        const uint32_t bufB = bufA + GTILE_W * 4u;

        // register-double-buffered fragments over 4 k16-steps
        uint32_t af[2][4][4], bf[2][4][4];
        #pragma unroll
        for (int mt = 0; mt < 4; mt++)
            ldsm4(af[0][mt], bufA + (uint32_t)(((rowA + mt * 16) * GSTR + colA) * 4));
        #pragma unroll
        for (int j = 0; j < 4; j++)
            ldsm4(bf[0][j], bufB + (uint32_t)(((rowB + j * 16) * GSTR + colB) * 4));

        #pragma unroll
        for (int ks = 0; ks < 4; ks++) {
            const int cur = ks & 1, nxt = cur ^ 1;
            if (ks < 3) {
                const int kk = (ks + 1) * 8;
                #pragma unroll
                for (int mt = 0; mt < 4; mt++)
                    ldsm4(af[nxt][mt], bufA + (uint32_t)(((rowA + mt * 16) * GSTR + kk + colA) * 4));
                #pragma unroll
                for (int j = 0; j < 4; j++)
                    ldsm4(bf[nxt][j], bufB + (uint32_t)(((rowB + j * 16) * GSTR + kk + colB) * 4));
            }
            #pragma unroll
            for (int mt = 0; mt < 4; mt++)
                #pragma unroll
                for (int j = 0; j < 4; j++) {
                    mma16816h(acc[mt][2 * j],     af[cur][mt], &bf[cur][j][0], acc[mt][2 * j]);
                    mma16816h(acc[mt][2 * j + 1], af[cur][mt], &bf[cur][j][2], acc[mt][2 * j + 1]);
                }
        }
    }

    // ---- epilogue
    #pragma unroll
    for (int mt = 0; mt < 4; mt++) {
        const int mloc = wm + mt * 16 + grp;
        #pragma unroll
        for (int nt = 0; nt < 8; nt++) {
            const int cn = wn + nt * 8 + 2 * tig;
            float2 v0 = make_float2(acc[mt][nt][0], acc[mt][nt][1]);
            float2 v1 = make_float2(acc[mt][nt][2], acc[mt][nt][3]);
            if (qkv_mode) {
                const int hg = col0 >> 7;
                const int sel = hg >> 4;
                const int h = hg & 15;
                #pragma unroll
                for (int rr = 0; rr < 2; rr++) {
                    int m = row0 + mloc + rr * 8;
                    int bb = m >> 11;
                    int t = m & (Tt - 1);
                    __half* dst = Ch + (size_t)sel * QKVS +
                                  ((size_t)(bb * Hh + h) * Tt + t) * HD + cn;
                    float2 vv = rr ? v1 : v0;
                    *(__half2*)dst = __floats2half2_rn(vv.x, vv.y);
                }
            } else {
                const int n = col0 + cn;
                if (bias) {
                    float2 bv = *(const float2*)(bias + n);
                    v0.x += bv.x; v0.y += bv.y;
                    v1.x += bv.x; v1.y += bv.y;
                }
                *(float2*)(Cf + (size_t)(row0 + mloc) * Dd + n) = v0;
                *(float2*)(Cf + (size_t)(row0 + mloc + 8) * Dd + n) = v1;
            }
        }
    }
}

// ===========================================================================
// fp16 tensor-core causal flash attention v2  [R14 proven — unchanged]
// ===========================================================================
#define AQ_STR 68
#define AV_STR 36
#define AKS_OFF (128 * AQ_STR)
#define AVS_OFF (AKS_OFF + 64 * AQ_STR)
#define APS_OFF (AVS_OFF + 64 * AQ_STR)
#define ATNH_SMEM ((APS_OFF + 128 * AV_STR) * 4)   // 88064 B

__global__ __launch_bounds__(256, 2) void attn_h(
    const __half* __restrict__ Q, const __half* __restrict__ K,
    const __half* __restrict__ V, __half* __restrict__ Out)
{
    extern __shared__ uint32_t sw[];
    const uint32_t abase = smem_u32(sw);

    const int tid = threadIdx.x;
    const int wid = tid >> 5;
    const int lane = tid & 31;
    const int grp = lane >> 2;
    const int tig = lane & 3;
    const int wm = wid * 16;
    const int qblk = (int)gridDim.x - 1 - (int)blockIdx.x;
    const int bh = blockIdx.y;
    const __half* Qp = Q + ((size_t)bh * Tt + qblk * 128) * HD;
    const __half* Kp = K + (size_t)bh * Tt * HD;
    const __half* Vp = V + (size_t)bh * Tt * HD;
    const float scale = 0.08838834764831845f;

    const int rowA = lane & 15;
    const int colA = ((lane >> 4) << 2);
    const int rowB = ((lane >> 4) << 3) + (lane & 7);
    const int colB = (((lane >> 3) & 1) << 2);
    const int krowT = lane & 15;
    const int hdoT = ((lane >> 4) << 3);

    #pragma unroll
    for (int i = 0; i < 8; i++) {
        int idx = tid + i * 256;
        int r = idx >> 4, c8 = idx & 15;
        *(uint4*)(sw + r * AQ_STR + c8 * 4) =
            *(const uint4*)(Qp + (size_t)r * HD + c8 * 8);
    }

    float o[16][4];
    #pragma unroll
    for (int nf = 0; nf < 16; nf++)
        #pragma unroll
        for (int e = 0; e < 4; e++) o[nf][e] = 0.f;
    float mi0 = -1e30f, mi1 = -1e30f, li0 = 0.f, li1 = 0.f;

    const int jmax = 2 * qblk + 1;
    const int r0g = qblk * 128 + wm + grp;
    const int r1g = r0g + 8;

    for (int jt = 0; jt <= jmax; jt++) {
        __syncthreads();
        #pragma unroll
        for (int i = 0; i < 4; i++) {
            int idx = tid + i * 256;
            int r = idx >> 4, c8 = idx & 15;
            cp16(abase + (uint32_t)((AKS_OFF + r * AQ_STR + c8 * 4) * 4),
                 Kp + (size_t)(jt * 64 + r) * HD + c8 * 8);
            cp16(abase + (uint32_t)((AVS_OFF + r * AQ_STR + c8 * 4) * 4),
                 Vp + (size_t)(jt * 64 + r) * HD + c8 * 8);
        }
        asm volatile("cp.async.commit_group;");
        asm volatile("cp.async.wait_group 0;");
        __syncthreads();

        float s[8][4];
        #pragma unroll
        for (int nf = 0; nf < 8; nf++)
            #pragma unroll
            for (int e = 0; e < 4; e++) s[nf][e] = 0.f;

        #pragma unroll
        for (int ks = 0; ks < 8; ks++) {
            const int kk = ks * 8;
            uint32_t a[4];
            ldsm4(a, abase + (uint32_t)(((wm + rowA) * AQ_STR + kk + colA) * 4));
            #pragma unroll
            for (int j = 0; j < 4; j++) {
                uint32_t bp[4];
                ldsm4(bp, abase + (uint32_t)((AKS_OFF + (rowB + j * 16) * AQ_STR + kk + colB) * 4));
                mma16816h(s[2 * j],     a, &bp[0], s[2 * j]);
                mma16816h(s[2 * j + 1], a, &bp[2], s[2 * j + 1]);
            }
        }

        #pragma unroll
        for (int nf = 0; nf < 8; nf++)
            #pragma unroll
            for (int e = 0; e < 4; e++) s[nf][e] *= scale;
        if (jt >= 2 * qblk) {
            #pragma unroll
            for (int nf = 0; nf < 8; nf++) {
                int c0 = jt * 64 + nf * 8 + 2 * tig;
                if (c0     > r0g) s[nf][0] = -1e30f;
                if (c0 + 1 > r0g) s[nf][1] = -1e30f;
                if (c0     > r1g) s[nf][2] = -1e30f;
                if (c0 + 1 > r1g) s[nf][3] = -1e30f;
            }
        }

        float m0 = -1e30f, m1 = -1e30f;
        #pragma unroll
        for (int nf = 0; nf < 8; nf++) {
            m0 = fmaxf(m0, fmaxf(s[nf][0], s[nf][1]));
            m1 = fmaxf(m1, fmaxf(s[nf][2], s[nf][3]));
        }
        m0 = fmaxf(m0, __shfl_xor_sync(0xffffffffu, m0, 1));
        m0 = fmaxf(m0, __shfl_xor_sync(0xffffffffu, m0, 2));
        m1 = fmaxf(m1, __shfl_xor_sync(0xffffffffu, m1, 1));
        m1 = fmaxf(m1, __shfl_xor_sync(0xffffffffu, m1, 2));
        float mn0 = fmaxf(mi0, m0), mn1 = fmaxf(mi1, m1);
        float al0 = __expf(mi0 - mn0), al1 = __expf(mi1 - mn1);
        float sum0 = 0.f, sum1 = 0.f;
        #pragma unroll
        for (int nf = 0; nf < 8; nf++) {
            s[nf][0] = __expf(s[nf][0] - mn0);
            s[nf][1] = __expf(s[nf][1] - mn0);
            s[nf][2] = __expf(s[nf][2] - mn1);
            s[nf][3] = __expf(s[nf][3] - mn1);
            sum0 += s[nf][0] + s[nf][1];
            sum1 += s[nf][2] + s[nf][3];
        }
        sum0 += __shfl_xor_sync(0xffffffffu, sum0, 1);
        sum0 += __shfl_xor_sync(0xffffffffu, sum0, 2);
        sum1 += __shfl_xor_sync(0xffffffffu, sum1, 1);
        sum1 += __shfl_xor_sync(0xffffffffu, sum1, 2);
        li0 = li0 * al0 + sum0;  mi0 = mn0;
        li1 = li1 * al1 + sum1;  mi1 = mn1;
        #pragma unroll
        for (int nf = 0; nf < 16; nf++) {
            o[nf][0] *= al0; o[nf][1] *= al0;
            o[nf][2] *= al1; o[nf][3] *= al1;
        }

        #pragma unroll
        for (int nf = 0; nf < 8; nf++) {
            ((__half2*)sw)[APS_OFF + (wm + grp) * AV_STR + nf * 4 + tig] =
                __floats2half2_rn(s[nf][0], s[nf][1]);
            ((__half2*)sw)[APS_OFF + (wm + grp + 8) * AV_STR + nf * 4 + tig] =
                __floats2half2_rn(s[nf][2], s[nf][3]);
        }
        __syncwarp();

        #pragma unroll
        for (int ks = 0; ks < 4; ks++) {
            uint32_t a[4];
            ldsm4(a, abase + (uint32_t)((APS_OFF + (wm + rowA) * AV_STR + ks * 8 + colA) * 4));
            const uint32_t vrow = abase +
                (uint32_t)((AVS_OFF + (ks * 16 + krowT) * AQ_STR) * 4);
            #pragma unroll
            for (int j = 0; j < 8; j++) {
                uint32_t bp[4];
                ldsm4t(bp, vrow + (uint32_t)((j * 16 + hdoT) * 2));
                mma16816h(o[2 * j],     a, &bp[0], o[2 * j]);
                mma16816h(o[2 * j + 1], a, &bp[2], o[2 * j + 1]);
            }
        }
        __syncwarp();
    }

    const int b = bh >> 4, h = bh & 15;
    const int t0 = qblk * 128 + wm + grp;
    float inv0 = 1.0f / li0, inv1 = 1.0f / li1;
    __half* O0 = Out + ((size_t)(b * Tt + t0)) * Dd + h * HD;
    #pragma unroll
    for (int nf = 0; nf < 16; nf++) {
        int c = nf * 8 + 2 * tig;
        *(__half2*)(O0 + c) = __floats2half2_rn(o[nf][0] * inv0, o[nf][1] * inv0);
        *(__half2*)(O0 + (size_t)8 * Dd + c) = __floats2half2_rn(o[nf][2] * inv1, o[nf][3] * inv1);
    }
}

// ---------------------------------------------------------------------------
extern "C" void kernel_launch(void* const* d_in, const int* in_sizes, int n_in,
                              void* d_out, int out_size)
{
    const float* x  = (const float*)d_in[0];
    const float* Wq = (const float*)d_in[1];
    const float* Wk = (const float*)d_in[2];
    const float* Wv = (const float*)d_in[3];
    const float* Wo = (const float*)d_in[4];
    const float* bo = (const float*)d_in[5];

    __half *qkvh, *xh, *wh, *ah;
    cudaGetSymbolAddress((void**)&qkvh, g_qkvh);
    cudaGetSymbolAddress((void**)&xh, g_xh);
    cudaGetSymbolAddress((void**)&wh, g_wh);
    cudaGetSymbolAddress((void**)&ah, g_ah);

    cudaFuncSetAttribute(tc_gemm_h, cudaFuncAttributeMaxDynamicSharedMemorySize, TCH_SMEM);
    cudaFuncSetAttribute(attn_h, cudaFuncAttributeMaxDynamicSharedMemorySize, ATNH_SMEM);

    // fp32 -> fp16 pre-pass (x + 4 weights)
    cvt_fp16<<<dim3(512, 5), 256>>>(x, Wq, Wk, Wv, Wo);

    const size_t WN = (size_t)Dd * Dd;

    // Merged QKV projection: one GEMM over N = 3*Dd (Wq|Wk|Wv contiguous)
    tc_gemm_h<<<dim3(3 * Dd / TBN, Mrows / TBM), 128, TCH_SMEM>>>(
        xh, wh, nullptr, nullptr, qkvh, 1);

    // fp16 tensor-core causal attention -> g_ah (fp16)
    attn_h<<<dim3(Tt / 128, Bz * Hh), 256, ATNH_SMEM>>>(
        qkvh, qkvh + QKVS, qkvh + 2 * QKVS, ah);

    // Output projection + bias (fp16 mma, fp32 out)
    tc_gemm_h<<<dim3(Dd / TBN, Mrows / TBM), 128, TCH_SMEM>>>(
        ah, wh + 3 * WN, bo, (float*)d_out, nullptr, 0);
}